// round 10
// baseline (speedup 1.0000x reference)
#include <cuda_runtime.h>

// NAM_42442866819214 — ONE fused kernel, HIERARCHICAL sync counters.
//
// R7/R9 post-mortem: fused versions measured ~15us because 512 atomicAdds to
// ONE address serialize in the LTS (~27-32cyc each ≈ 8-9us tail), plus 128
// serialized publisher adds on the release path. Fix: two-level counters on
// 128B-strided addresses (parallel LTS slices), single-word release flag.
//
// Math collapse (per-feature, valid when b1[f,:]==0 && b2[f,:]==0, verified
// at runtime into g_mode[f]):
//   relu(x*w) = x * (x>0 ? max(w,0) : min(w,0))
//   contrib(b,f) = x * (x>0 ? dpos[f] : dneg[f]) + b3[f]
//
// 512 blocks x 256 thr (<=64 regs -> all wave-1 resident; publishers are
// bids 0-127 so the release cannot deadlock):
//   every block : prefetch its 16 input rows + b3 + bias FIRST
//   blocks 0-127: fold W1,W2,W3 -> dpos/dneg for one feature, publish,
//                 count via g_ready_grp[8] -> g_rfin -> g_go
//   every block : tid0 polls g_go (cg load, 128->512ns backoff), syncthreads
//   every block : piecewise-linear map, store contribs, row-sum via shuffles
//   done/reset  : g_done_grp[32] -> g_fin -> last thread zeroes all state
//                 (graph-replay deterministic)

#define NB   8192
#define NF   128
#define NH1  64
#define NH2  32
#define GRID 512
#define RPB  16    // rows per block = 8 warps * 2 rows
#define STRIDE 32  // 32 ints = 128B between counter addresses

__device__ float g_dpos[NF];
__device__ float g_dneg[NF];
__device__ int   g_mode[NF];
__device__ int   g_ready_grp[8  * STRIDE];  // publisher group counters
__device__ int   g_rfin;                    // publisher finisher count
__device__ int   g_go;                      // release flag
__device__ int   g_done_grp[32 * STRIDE];   // done group counters
__device__ int   g_fin;                     // done finisher count

__device__ __forceinline__ int ld_cg(const int* p) {
    int v;
    asm volatile("ld.global.cg.s32 %0, [%1];" : "=r"(v) : "l"(p) : "memory");
    return v;
}

// Dead unless b1/b2 nonzero; kept for correctness on arbitrary bias values.
__device__ __noinline__ float mlp_full(float x, int f,
                                       const float* __restrict__ W1,
                                       const float* __restrict__ b1,
                                       const float* __restrict__ W2,
                                       const float* __restrict__ b2,
                                       const float* __restrict__ W3) {
    float acc = 0.f;
    for (int k = 0; k < NH2; k++) {
        float a = b2[f * NH2 + k];
        for (int i = 0; i < NH1; i++) {
            float h1 = fmaxf(fmaf(x, W1[f * NH1 + i], b1[f * NH1 + i]), 0.f);
            a = fmaf(h1, W2[(f * NH1 + i) * NH2 + k], a);
        }
        acc = fmaf(fmaxf(a, 0.f), W3[f * NH2 + k], acc);
    }
    return acc;
}

__global__ void __launch_bounds__(256, 4)
nam_fused(const float* __restrict__ inputs,
          const float* __restrict__ W1,
          const float* __restrict__ b1,
          const float* __restrict__ W2,
          const float* __restrict__ b2,
          const float* __restrict__ W3,
          const float* __restrict__ b3,
          const float* __restrict__ bias,
          float* __restrict__ out) {
    const int tid  = threadIdx.x;
    const int lane = tid & 31;
    const int warp = tid >> 5;           // 0..7
    const int b0   = blockIdx.x * RPB + warp;
    const int f0   = lane * 4;

    const float4* in4 = (const float4*)inputs;
    float4*       c4  = (float4*)(out + NB);

    // ---- prefetch (independent of precompute) — issue FIRST --------------
    float4 x0 = in4[b0 * (NF / 4) + lane];
    float4 x1 = in4[(b0 + 8) * (NF / 4) + lane];
    const float4 b34   = ((const float4*)b3)[lane];
    const float  bias0 = bias[0];

    // ---- precompute (blocks 0..127, one feature each) --------------------
    __shared__ float s_cp[8][32], s_cn[8][32];
    __shared__ int   s_nz[8];
    if (blockIdx.x < NF) {
        const int f = blockIdx.x;
        const int k = lane;

        int nz = 0;
        if (tid < NH1)            nz = (b1[f * NH1 + tid] != 0.f);
        else if (tid < NH1 + NH2) nz = (b2[f * NH2 + tid - NH1] != 0.f);
        int wnz = __ballot_sync(0xffffffffu, nz) ? 1 : 0;  // all lanes execute

        float cp = 0.f, cn = 0.f;
#pragma unroll
        for (int j = 0; j < 8; j++) {
            const int i = warp * 8 + j;
            float w  = W1[f * NH1 + i];               // warp-uniform
            float w2 = W2[(f * NH1 + i) * NH2 + k];   // coalesced
            cp = fmaf(w2, fmaxf(w, 0.f), cp);
            cn = fmaf(w2, fminf(w, 0.f), cn);
        }
        s_cp[warp][k] = cp;
        s_cn[warp][k] = cn;
        if (lane == 0) s_nz[warp] = wnz;
        __syncthreads();

        if (warp == 0) {
            float tcp = 0.f, tcn = 0.f;
#pragma unroll
            for (int w8 = 0; w8 < 8; w8++) {
                tcp += s_cp[w8][k];
                tcn += s_cn[w8][k];
            }
            float w3 = W3[f * NH2 + k];
            float dp = w3 * fmaxf(tcp, 0.f);
            float dn = w3 * fminf(tcn, 0.f);
#pragma unroll
            for (int o = 16; o > 0; o >>= 1) {
                dp += __shfl_xor_sync(0xffffffffu, dp, o);
                dn += __shfl_xor_sync(0xffffffffu, dn, o);
            }
            if (k == 0) {
                g_dpos[f] = dp;
                g_dneg[f] = dn;
                g_mode[f] = s_nz[0] | s_nz[1] | s_nz[2] | s_nz[3] |
                            s_nz[4] | s_nz[5] | s_nz[6] | s_nz[7];
                __threadfence();
                // hierarchical publish count: 8 parallel groups of 16
                if (atomicAdd(&g_ready_grp[(f & 7) * STRIDE], 1) == 15) {
                    if (atomicAdd(&g_rfin, 1) == 7) {
                        atomicExch(&g_go, 1);   // release
                    }
                }
            }
        }
    }

    // ---- low-pressure wait for release ------------------------------------
    if (tid == 0) {
        if (ld_cg(&g_go) == 0) {
            unsigned ns = 128;
            do {
                __nanosleep(ns);
                if (ns < 512) ns <<= 1;
            } while (ld_cg(&g_go) == 0);
        }
    }
    __syncthreads();

    // ---- stream ------------------------------------------------------------
    const float4 dp4 = __ldcg(&((const float4*)g_dpos)[lane]);
    const float4 dn4 = __ldcg(&((const float4*)g_dneg)[lane]);
    const int4   m4  = __ldcg(&((const int4*)g_mode)[lane]);
    const bool fast = (m4.x | m4.y | m4.z | m4.w) == 0;

#pragma unroll
    for (int r = 0; r < 2; r++) {
        const int b = b0 + r * 8;
        const float4 x = r ? x1 : x0;
        float4 c;
        if (fast) {
            c.x = fmaf(x.x, (x.x > 0.f ? dp4.x : dn4.x), b34.x);
            c.y = fmaf(x.y, (x.y > 0.f ? dp4.y : dn4.y), b34.y);
            c.z = fmaf(x.z, (x.z > 0.f ? dp4.z : dn4.z), b34.z);
            c.w = fmaf(x.w, (x.w > 0.f ? dp4.w : dn4.w), b34.w);
        } else {
            c.x = mlp_full(x.x, f0 + 0, W1, b1, W2, b2, W3) + b34.x;
            c.y = mlp_full(x.y, f0 + 1, W1, b1, W2, b2, W3) + b34.y;
            c.z = mlp_full(x.z, f0 + 2, W1, b1, W2, b2, W3) + b34.z;
            c.w = mlp_full(x.w, f0 + 3, W1, b1, W2, b2, W3) + b34.w;
        }
        c4[b * (NF / 4) + lane] = c;

        float s = (c.x + c.y) + (c.z + c.w);
#pragma unroll
        for (int o = 16; o > 0; o >>= 1)
            s += __shfl_xor_sync(0xffffffffu, s, o);
        if (lane == 0) out[b] = s + bias0;
    }

    // ---- hierarchical done-count + reset (replay-deterministic) -----------
    __syncthreads();
    if (tid == 0) {
        // 32 parallel groups of 16 blocks each
        if (atomicAdd(&g_done_grp[(blockIdx.x & 31) * STRIDE], 1) == 15) {
            if (atomicAdd(&g_fin, 1) == 31) {
                // last finisher: zero ALL sync state for the next replay
#pragma unroll
                for (int i = 0; i < 8; i++)  g_ready_grp[i * STRIDE] = 0;
#pragma unroll
                for (int i = 0; i < 32; i++) g_done_grp[i * STRIDE] = 0;
                g_rfin = 0;
                g_go   = 0;
                g_fin  = 0;
                __threadfence();
            }
        }
    }
}

extern "C" void kernel_launch(void* const* d_in, const int* in_sizes, int n_in,
                              void* d_out, int out_size) {
    const float* inputs = (const float*)d_in[0];
    const float* W1     = (const float*)d_in[1];
    const float* b1     = (const float*)d_in[2];
    const float* W2     = (const float*)d_in[3];
    const float* b2     = (const float*)d_in[4];
    const float* W3     = (const float*)d_in[5];
    const float* b3     = (const float*)d_in[6];
    const float* bias   = (const float*)d_in[7];

    nam_fused<<<GRID, 256>>>(inputs, W1, b1, W2, b2, W3, b3, bias,
                             (float*)d_out);
}

// round 12
// speedup vs baseline: 1.1577x; 1.1577x over previous
#include <cuda_runtime.h>

// NAM_42442866819214 — ONE fused kernel, busy-poll with ACQUIRE semantics.
//
// R11 failed correctness: relaxed ld.cg poll + immediate coefficient reads =
// no ordering (publisher's release was fine; consumer lacked acquire). Fix:
// poll with ld.global.acquire.gpu, then __syncthreads (CTA fence) before any
// thread reads the coefficients. This finally tests the R11 hypothesis that
// __nanosleep wake quantization (~10+us) caused every fused variant's 13-19us.
//
// Math collapse (per-feature, valid when b1[f,:]==0 && b2[f,:]==0, verified
// at runtime into g_mode[f]):
//   relu(x*w) = x * (x>0 ? max(w,0) : min(w,0))
//   contrib(b,f) = x * (x>0 ? dpos[f] : dneg[f]) + b3[f]
//
// 512 blocks x 256 thr (<=64 regs -> all wave-1 resident; publisher blocks
// are bids 0-127, placed first -> release cannot deadlock).

#define NB   8192
#define NF   128
#define NH1  64
#define NH2  32
#define GRID 512
#define RPB  16    // rows per block = 8 warps * 2 rows
#define STRIDE 32  // 32 ints = 128B between counter addresses

__device__ float g_dpos[NF];
__device__ float g_dneg[NF];
__device__ int   g_mode[NF];
__device__ int   g_ready_grp[8  * STRIDE];  // publisher group counters
__device__ int   g_rfin;                    // publisher finisher count
__device__ int   g_go;                      // release flag
__device__ int   g_done_grp[32 * STRIDE];   // done group counters
__device__ int   g_fin;                     // done finisher count

// acquire-load: orders ALL subsequent loads in this thread after the flag read
__device__ __forceinline__ int ld_acq(const int* p) {
    int v;
    asm volatile("ld.global.acquire.gpu.s32 %0, [%1];"
                 : "=r"(v) : "l"(p) : "memory");
    return v;
}

// Dead unless b1/b2 nonzero; kept for correctness on arbitrary bias values.
__device__ __noinline__ float mlp_full(float x, int f,
                                       const float* __restrict__ W1,
                                       const float* __restrict__ b1,
                                       const float* __restrict__ W2,
                                       const float* __restrict__ b2,
                                       const float* __restrict__ W3) {
    float acc = 0.f;
    for (int k = 0; k < NH2; k++) {
        float a = b2[f * NH2 + k];
        for (int i = 0; i < NH1; i++) {
            float h1 = fmaxf(fmaf(x, W1[f * NH1 + i], b1[f * NH1 + i]), 0.f);
            a = fmaf(h1, W2[(f * NH1 + i) * NH2 + k], a);
        }
        acc = fmaf(fmaxf(a, 0.f), W3[f * NH2 + k], acc);
    }
    return acc;
}

__global__ void __launch_bounds__(256, 4)
nam_fused(const float* __restrict__ inputs,
          const float* __restrict__ W1,
          const float* __restrict__ b1,
          const float* __restrict__ W2,
          const float* __restrict__ b2,
          const float* __restrict__ W3,
          const float* __restrict__ b3,
          const float* __restrict__ bias,
          float* __restrict__ out) {
    const int tid  = threadIdx.x;
    const int lane = tid & 31;
    const int warp = tid >> 5;           // 0..7
    const int b0   = blockIdx.x * RPB + warp;
    const int f0   = lane * 4;

    const float4* in4 = (const float4*)inputs;
    float4*       c4  = (float4*)(out + NB);

    // ---- prefetch (independent of precompute) — issue FIRST --------------
    float4 x0 = in4[b0 * (NF / 4) + lane];
    float4 x1 = in4[(b0 + 8) * (NF / 4) + lane];
    const float4 b34   = ((const float4*)b3)[lane];
    const float  bias0 = bias[0];

    // ---- precompute (blocks 0..127, one feature each) --------------------
    __shared__ float s_cp[8][32], s_cn[8][32];
    __shared__ int   s_nz[8];
    if (blockIdx.x < NF) {
        const int f = blockIdx.x;
        const int k = lane;

        int nz = 0;
        if (tid < NH1)            nz = (b1[f * NH1 + tid] != 0.f);
        else if (tid < NH1 + NH2) nz = (b2[f * NH2 + tid - NH1] != 0.f);
        int wnz = __ballot_sync(0xffffffffu, nz) ? 1 : 0;  // all lanes execute

        float cp = 0.f, cn = 0.f;
#pragma unroll
        for (int j = 0; j < 8; j++) {
            const int i = warp * 8 + j;
            float w  = W1[f * NH1 + i];               // warp-uniform
            float w2 = W2[(f * NH1 + i) * NH2 + k];   // coalesced
            cp = fmaf(w2, fmaxf(w, 0.f), cp);
            cn = fmaf(w2, fminf(w, 0.f), cn);
        }
        s_cp[warp][k] = cp;
        s_cn[warp][k] = cn;
        if (lane == 0) s_nz[warp] = wnz;
        __syncthreads();

        if (warp == 0) {
            float tcp = 0.f, tcn = 0.f;
#pragma unroll
            for (int w8 = 0; w8 < 8; w8++) {
                tcp += s_cp[w8][k];
                tcn += s_cn[w8][k];
            }
            float w3 = W3[f * NH2 + k];
            float dp = w3 * fmaxf(tcp, 0.f);
            float dn = w3 * fminf(tcn, 0.f);
#pragma unroll
            for (int o = 16; o > 0; o >>= 1) {
                dp += __shfl_xor_sync(0xffffffffu, dp, o);
                dn += __shfl_xor_sync(0xffffffffu, dn, o);
            }
            if (k == 0) {
                g_dpos[f] = dp;
                g_dneg[f] = dn;
                g_mode[f] = s_nz[0] | s_nz[1] | s_nz[2] | s_nz[3] |
                            s_nz[4] | s_nz[5] | s_nz[6] | s_nz[7];
                __threadfence();   // release: coeffs visible before counts
                // hierarchical publish count: 8 parallel groups of 16
                if (atomicAdd(&g_ready_grp[(f & 7) * STRIDE], 1) == 15) {
                    if (atomicAdd(&g_rfin, 1) == 7) {
                        atomicExch(&g_go, 1);   // release flag
                    }
                }
            }
        }
    }

    // ---- busy-poll with ACQUIRE (no nanosleep) -----------------------------
    if (tid == 0) {
        while (ld_acq(&g_go) == 0) { }
    }
    __syncthreads();   // CTA fence: broadcasts tid0's acquired view

    // ---- stream ------------------------------------------------------------
    const float4 dp4 = __ldcg(&((const float4*)g_dpos)[lane]);
    const float4 dn4 = __ldcg(&((const float4*)g_dneg)[lane]);
    const int4   m4  = __ldcg(&((const int4*)g_mode)[lane]);
    const bool fast = (m4.x | m4.y | m4.z | m4.w) == 0;

#pragma unroll
    for (int r = 0; r < 2; r++) {
        const int b = b0 + r * 8;
        const float4 x = r ? x1 : x0;
        float4 c;
        if (fast) {
            c.x = fmaf(x.x, (x.x > 0.f ? dp4.x : dn4.x), b34.x);
            c.y = fmaf(x.y, (x.y > 0.f ? dp4.y : dn4.y), b34.y);
            c.z = fmaf(x.z, (x.z > 0.f ? dp4.z : dn4.z), b34.z);
            c.w = fmaf(x.w, (x.w > 0.f ? dp4.w : dn4.w), b34.w);
        } else {
            c.x = mlp_full(x.x, f0 + 0, W1, b1, W2, b2, W3) + b34.x;
            c.y = mlp_full(x.y, f0 + 1, W1, b1, W2, b2, W3) + b34.y;
            c.z = mlp_full(x.z, f0 + 2, W1, b1, W2, b2, W3) + b34.z;
            c.w = mlp_full(x.w, f0 + 3, W1, b1, W2, b2, W3) + b34.w;
        }
        c4[b * (NF / 4) + lane] = c;

        float s = (c.x + c.y) + (c.z + c.w);
#pragma unroll
        for (int o = 16; o > 0; o >>= 1)
            s += __shfl_xor_sync(0xffffffffu, s, o);
        if (lane == 0) out[b] = s + bias0;
    }

    // ---- hierarchical done-count + reset (replay-deterministic) -----------
    __syncthreads();
    if (tid == 0) {
        if (atomicAdd(&g_done_grp[(blockIdx.x & 31) * STRIDE], 1) == 15) {
            if (atomicAdd(&g_fin, 1) == 31) {
#pragma unroll
                for (int i = 0; i < 8; i++)  g_ready_grp[i * STRIDE] = 0;
#pragma unroll
                for (int i = 0; i < 32; i++) g_done_grp[i * STRIDE] = 0;
                g_rfin = 0;
                g_go   = 0;
                g_fin  = 0;
                __threadfence();
            }
        }
    }
}

extern "C" void kernel_launch(void* const* d_in, const int* in_sizes, int n_in,
                              void* d_out, int out_size) {
    const float* inputs = (const float*)d_in[0];
    const float* W1     = (const float*)d_in[1];
    const float* b1     = (const float*)d_in[2];
    const float* W2     = (const float*)d_in[3];
    const float* b2     = (const float*)d_in[4];
    const float* W3     = (const float*)d_in[5];
    const float* b3     = (const float*)d_in[6];
    const float* bias   = (const float*)d_in[7];

    nam_fused<<<GRID, 256>>>(inputs, W1, b1, W2, b2, W3, b3, bias,
                             (float*)d_out);
}

// round 13
// speedup vs baseline: 1.3400x; 1.1575x over previous
#include <cuda_runtime.h>

// NAM_42442866819214 — ONE fused kernel. R13: coefficient reads via L1.
//
// ROOT CAUSE of every fused variant's 13-19us (R2/R7/R9/R10/R12): the
// coefficient broadcast used __ldcg (L1-bypass). 131072 threads x 48B of
// per-lane reads against the SAME ~12 L2 lines = ~6MB of traffic serialized
// through a few LTS slices (~32B/cyc each) ≈ 8-15us. The 2-node versions
// used plain (L1-cached) loads — that was the whole difference, not sync.
// Fix: plain loads after acquire-poll + __syncthreads (L1 flushed per
// launch and never touched these lines pre-flag, so no stale-copy hazard).
//
// Math collapse (per-feature, valid when b1[f,:]==0 && b2[f,:]==0, verified
// at runtime into g_mode[f]):
//   relu(x*w) = x * (x>0 ? max(w,0) : min(w,0))
//   contrib(b,f) = x * (x>0 ? dpos[f] : dneg[f]) + b3[f]
//
// 512 blocks x 256 thr (<=64 regs -> all wave-1 resident; publisher blocks
// are bids 0-127, placed first -> release cannot deadlock).

#define NB   8192
#define NF   128
#define NH1  64
#define NH2  32
#define GRID 512
#define RPB  16    // rows per block = 8 warps * 2 rows
#define STRIDE 32  // 32 ints = 128B between counter addresses

__device__ float g_dpos[NF];
__device__ float g_dneg[NF];
__device__ int   g_mode[NF];
__device__ int   g_ready_grp[8  * STRIDE];  // publisher group counters
__device__ int   g_rfin;                    // publisher finisher count
__device__ int   g_go;                      // release flag
__device__ int   g_done_grp[32 * STRIDE];   // done group counters
__device__ int   g_fin;                     // done finisher count

// acquire-load for the flag poll only
__device__ __forceinline__ int ld_acq(const int* p) {
    int v;
    asm volatile("ld.global.acquire.gpu.s32 %0, [%1];"
                 : "=r"(v) : "l"(p) : "memory");
    return v;
}

// Dead unless b1/b2 nonzero; kept for correctness on arbitrary bias values.
__device__ __noinline__ float mlp_full(float x, int f,
                                       const float* __restrict__ W1,
                                       const float* __restrict__ b1,
                                       const float* __restrict__ W2,
                                       const float* __restrict__ b2,
                                       const float* __restrict__ W3) {
    float acc = 0.f;
    for (int k = 0; k < NH2; k++) {
        float a = b2[f * NH2 + k];
        for (int i = 0; i < NH1; i++) {
            float h1 = fmaxf(fmaf(x, W1[f * NH1 + i], b1[f * NH1 + i]), 0.f);
            a = fmaf(h1, W2[(f * NH1 + i) * NH2 + k], a);
        }
        acc = fmaf(fmaxf(a, 0.f), W3[f * NH2 + k], acc);
    }
    return acc;
}

__global__ void __launch_bounds__(256, 4)
nam_fused(const float* __restrict__ inputs,
          const float* __restrict__ W1,
          const float* __restrict__ b1,
          const float* __restrict__ W2,
          const float* __restrict__ b2,
          const float* __restrict__ W3,
          const float* __restrict__ b3,
          const float* __restrict__ bias,
          float* __restrict__ out) {
    const int tid  = threadIdx.x;
    const int lane = tid & 31;
    const int warp = tid >> 5;           // 0..7
    const int b0   = blockIdx.x * RPB + warp;
    const int f0   = lane * 4;

    const float4* in4 = (const float4*)inputs;
    float4*       c4  = (float4*)(out + NB);

    // ---- prefetch (independent of precompute) — issue FIRST --------------
    float4 x0 = in4[b0 * (NF / 4) + lane];
    float4 x1 = in4[(b0 + 8) * (NF / 4) + lane];
    const float4 b34   = ((const float4*)b3)[lane];
    const float  bias0 = bias[0];

    // ---- precompute (blocks 0..127, one feature each) --------------------
    __shared__ float s_cp[8][32], s_cn[8][32];
    __shared__ int   s_nz[8];
    if (blockIdx.x < NF) {
        const int f = blockIdx.x;
        const int k = lane;

        int nz = 0;
        if (tid < NH1)            nz = (b1[f * NH1 + tid] != 0.f);
        else if (tid < NH1 + NH2) nz = (b2[f * NH2 + tid - NH1] != 0.f);
        int wnz = __ballot_sync(0xffffffffu, nz) ? 1 : 0;  // all lanes execute

        float cp = 0.f, cn = 0.f;
#pragma unroll
        for (int j = 0; j < 8; j++) {
            const int i = warp * 8 + j;
            float w  = W1[f * NH1 + i];               // warp-uniform
            float w2 = W2[(f * NH1 + i) * NH2 + k];   // coalesced
            cp = fmaf(w2, fmaxf(w, 0.f), cp);
            cn = fmaf(w2, fminf(w, 0.f), cn);
        }
        s_cp[warp][k] = cp;
        s_cn[warp][k] = cn;
        if (lane == 0) s_nz[warp] = wnz;
        __syncthreads();

        if (warp == 0) {
            float tcp = 0.f, tcn = 0.f;
#pragma unroll
            for (int w8 = 0; w8 < 8; w8++) {
                tcp += s_cp[w8][k];
                tcn += s_cn[w8][k];
            }
            float w3 = W3[f * NH2 + k];
            float dp = w3 * fmaxf(tcp, 0.f);
            float dn = w3 * fminf(tcn, 0.f);
#pragma unroll
            for (int o = 16; o > 0; o >>= 1) {
                dp += __shfl_xor_sync(0xffffffffu, dp, o);
                dn += __shfl_xor_sync(0xffffffffu, dn, o);
            }
            if (k == 0) {
                g_dpos[f] = dp;
                g_dneg[f] = dn;
                g_mode[f] = s_nz[0] | s_nz[1] | s_nz[2] | s_nz[3] |
                            s_nz[4] | s_nz[5] | s_nz[6] | s_nz[7];
                __threadfence();   // release: coeffs visible before counts
                if (atomicAdd(&g_ready_grp[(f & 7) * STRIDE], 1) == 15) {
                    if (atomicAdd(&g_rfin, 1) == 7) {
                        atomicExch(&g_go, 1);   // release flag
                    }
                }
            }
        }
    }

    // ---- busy-poll with ACQUIRE -------------------------------------------
    if (tid == 0) {
        while (ld_acq(&g_go) == 0) { }
    }
    __syncthreads();   // CTA fence: broadcasts tid0's acquired view

    // ---- stream: coefficients via PLAIN (L1-cacheable) loads ---------------
    const float4 dp4 = ((const float4*)g_dpos)[lane];
    const float4 dn4 = ((const float4*)g_dneg)[lane];
    const int4   m4  = ((const int4*)g_mode)[lane];
    const bool fast = (m4.x | m4.y | m4.z | m4.w) == 0;

#pragma unroll
    for (int r = 0; r < 2; r++) {
        const int b = b0 + r * 8;
        const float4 x = r ? x1 : x0;
        float4 c;
        if (fast) {
            c.x = fmaf(x.x, (x.x > 0.f ? dp4.x : dn4.x), b34.x);
            c.y = fmaf(x.y, (x.y > 0.f ? dp4.y : dn4.y), b34.y);
            c.z = fmaf(x.z, (x.z > 0.f ? dp4.z : dn4.z), b34.z);
            c.w = fmaf(x.w, (x.w > 0.f ? dp4.w : dn4.w), b34.w);
        } else {
            c.x = mlp_full(x.x, f0 + 0, W1, b1, W2, b2, W3) + b34.x;
            c.y = mlp_full(x.y, f0 + 1, W1, b1, W2, b2, W3) + b34.y;
            c.z = mlp_full(x.z, f0 + 2, W1, b1, W2, b2, W3) + b34.z;
            c.w = mlp_full(x.w, f0 + 3, W1, b1, W2, b2, W3) + b34.w;
        }
        c4[b * (NF / 4) + lane] = c;

        float s = (c.x + c.y) + (c.z + c.w);
#pragma unroll
        for (int o = 16; o > 0; o >>= 1)
            s += __shfl_xor_sync(0xffffffffu, s, o);
        if (lane == 0) out[b] = s + bias0;
    }

    // ---- hierarchical done-count + reset (replay-deterministic) -----------
    __syncthreads();
    if (tid == 0) {
        if (atomicAdd(&g_done_grp[(blockIdx.x & 31) * STRIDE], 1) == 15) {
            if (atomicAdd(&g_fin, 1) == 31) {
#pragma unroll
                for (int i = 0; i < 8; i++)  g_ready_grp[i * STRIDE] = 0;
#pragma unroll
                for (int i = 0; i < 32; i++) g_done_grp[i * STRIDE] = 0;
                g_rfin = 0;
                g_go   = 0;
                g_fin  = 0;
                __threadfence();
            }
        }
    }
}

extern "C" void kernel_launch(void* const* d_in, const int* in_sizes, int n_in,
                              void* d_out, int out_size) {
    const float* inputs = (const float*)d_in[0];
    const float* W1     = (const float*)d_in[1];
    const float* b1     = (const float*)d_in[2];
    const float* W2     = (const float*)d_in[3];
    const float* b2     = (const float*)d_in[4];
    const float* W3     = (const float*)d_in[5];
    const float* b3     = (const float*)d_in[6];
    const float* bias   = (const float*)d_in[7];

    nam_fused<<<GRID, 256>>>(inputs, W1, b1, W2, b2, W3, b3, bias,
                             (float*)d_out);
}

// round 14
// speedup vs baseline: 1.9779x; 1.4760x over previous
#include <cuda_runtime.h>

// NAM_42442866819214 — FINAL: 2 kernels + PDL (measured-best R3 config).
//
// Record: 2-node PDL = 8.67-8.96us across three very different internal
// configs (structure-dominated floor). Fused single-kernel = 12.8-18.9us
// across six sync designs (flat/hierarchical atomics, backoff, acquire,
// L1-cached broadcast) — abandoned. This is the 8.67us measured winner.
//
// Math collapse (per-feature, valid when b1[f,:]==0 && b2[f,:]==0, verified
// at runtime into g_mode[f]):
//   relu(x*w) = x * (x>0 ? max(w,0) : min(w,0))
//   contrib(b,f) = x * (x>0 ? dpos[f] : dneg[f]) + b3[f]
//
// nam_pre : folds W1,W2,W3 -> dpos/dneg (one warp per feature), PDL-triggers
//           at entry so nam_main's launch+prefetch overlaps it.
// nam_main: 256 blocks x 128 thr (all wave-1 resident). Warp w owns rows
//           {bid*32 + it*4 + w}; inputs prefetched into registers BEFORE
//           cudaGridDependencySynchronize(); post-sync work = FMA + stores
//           + shuffle row-reduction.

#define NB   8192
#define NF   128
#define NH1  64
#define NH2  32
#define GRID 256            // NB / ROWS_PER_BLOCK
#define ROWS_PER_BLOCK 32   // 4 warps * 8 rows

__device__ float g_dpos[NF];
__device__ float g_dneg[NF];
__device__ int   g_mode[NF];   // 0 = fast path valid (rewritten every launch)

// ---------------------------------------------------------------- precompute
__global__ void __launch_bounds__(32)
nam_pre(const float* __restrict__ W1,
        const float* __restrict__ b1,
        const float* __restrict__ W2,
        const float* __restrict__ b2,
        const float* __restrict__ W3) {
    cudaTriggerProgrammaticLaunchCompletion();   // let nam_main start now

    const int f = blockIdx.x;
    const int k = threadIdx.x;  // H2 unit, 0..31

    int nz = (b1[f * NH1 + k]      != 0.f) |
             (b1[f * NH1 + 32 + k] != 0.f) |
             (b2[f * NH2 + k]      != 0.f);
    unsigned bal = __ballot_sync(0xffffffffu, nz);

    float cp = 0.f, cn = 0.f;
#pragma unroll
    for (int i = 0; i < NH1; i++) {
        float w  = W1[f * NH1 + i];               // warp-uniform
        float w2 = W2[(f * NH1 + i) * NH2 + k];   // coalesced 128B lines
        cp = fmaf(w2, fmaxf(w, 0.f), cp);
        cn = fmaf(w2, fminf(w, 0.f), cn);
    }
    float w3 = W3[f * NH2 + k];
    float dp = w3 * fmaxf(cp, 0.f);   // x>0: relu(x*cp) = x*max(cp,0)
    float dn = w3 * fminf(cn, 0.f);   // x<0: relu(x*cn) = x*min(cn,0)
#pragma unroll
    for (int o = 16; o > 0; o >>= 1) {
        dp += __shfl_xor_sync(0xffffffffu, dp, o);
        dn += __shfl_xor_sync(0xffffffffu, dn, o);
    }
    if (k == 0) {
        g_dpos[f] = dp;
        g_dneg[f] = dn;
        g_mode[f] = bal ? 1 : 0;
    }
}

// ------------------------------------------------------------------ fallback
// Full per-element MLP. Dead unless b1/b2 are nonzero; keeps the kernel
// correct for arbitrary bias values.
__device__ __noinline__ float mlp_full(float x, int f,
                                       const float* __restrict__ W1,
                                       const float* __restrict__ b1,
                                       const float* __restrict__ W2,
                                       const float* __restrict__ b2,
                                       const float* __restrict__ W3) {
    float acc = 0.f;
    for (int k = 0; k < NH2; k++) {
        float a = b2[f * NH2 + k];
        for (int i = 0; i < NH1; i++) {
            float h1 = fmaxf(fmaf(x, W1[f * NH1 + i], b1[f * NH1 + i]), 0.f);
            a = fmaf(h1, W2[(f * NH1 + i) * NH2 + k], a);
        }
        acc = fmaf(fmaxf(a, 0.f), W3[f * NH2 + k], acc);
    }
    return acc;
}

// ---------------------------------------------------------------------- main
__global__ void __launch_bounds__(128)
nam_main(const float* __restrict__ inputs,
         const float* __restrict__ W1,
         const float* __restrict__ b1,
         const float* __restrict__ W2,
         const float* __restrict__ b2,
         const float* __restrict__ W3,
         const float* __restrict__ b3,
         const float* __restrict__ bias,
         float* __restrict__ out) {
    const int lane = threadIdx.x & 31;
    const int warp = threadIdx.x >> 5;   // 0..3
    const int f0   = lane * 4;

    const float4* in4 = (const float4*)inputs;
    float4*       c4  = (float4*)(out + NB);

    // ---- prefetch input rows (independent of nam_pre) --------------------
    float4 x[8];
#pragma unroll
    for (int it = 0; it < 8; it++) {
        const int b = blockIdx.x * ROWS_PER_BLOCK + it * 4 + warp;
        x[it] = in4[b * (NF / 4) + lane];
    }

    // ---- wait for nam_pre's results to be visible -------------------------
    cudaGridDependencySynchronize();

    const float4 dp4 = ((const float4*)g_dpos)[lane];
    const float4 dn4 = ((const float4*)g_dneg)[lane];
    const int4   m4  = ((const int4*)g_mode)[lane];
    const float4 b34 = ((const float4*)b3)[lane];
    const float  bias0 = bias[0];
    const bool   fast = (m4.x | m4.y | m4.z | m4.w) == 0;

#pragma unroll
    for (int it = 0; it < 8; it++) {
        const int b = blockIdx.x * ROWS_PER_BLOCK + it * 4 + warp;
        float4 c;
        if (fast) {
            c.x = fmaf(x[it].x, (x[it].x > 0.f ? dp4.x : dn4.x), b34.x);
            c.y = fmaf(x[it].y, (x[it].y > 0.f ? dp4.y : dn4.y), b34.y);
            c.z = fmaf(x[it].z, (x[it].z > 0.f ? dp4.z : dn4.z), b34.z);
            c.w = fmaf(x[it].w, (x[it].w > 0.f ? dp4.w : dn4.w), b34.w);
        } else {
            c.x = mlp_full(x[it].x, f0 + 0, W1, b1, W2, b2, W3) + b34.x;
            c.y = mlp_full(x[it].y, f0 + 1, W1, b1, W2, b2, W3) + b34.y;
            c.z = mlp_full(x[it].z, f0 + 2, W1, b1, W2, b2, W3) + b34.z;
            c.w = mlp_full(x[it].w, f0 + 3, W1, b1, W2, b2, W3) + b34.w;
        }
        c4[b * (NF / 4) + lane] = c;

        float s = (c.x + c.y) + (c.z + c.w);
#pragma unroll
        for (int o = 16; o > 0; o >>= 1)
            s += __shfl_xor_sync(0xffffffffu, s, o);
        if (lane == 0) out[b] = s + bias0;
    }
}

// -------------------------------------------------------------------- launch
extern "C" void kernel_launch(void* const* d_in, const int* in_sizes, int n_in,
                              void* d_out, int out_size) {
    const float* inputs = (const float*)d_in[0];
    const float* W1     = (const float*)d_in[1];
    const float* b1     = (const float*)d_in[2];
    const float* W2     = (const float*)d_in[3];
    const float* b2     = (const float*)d_in[4];
    const float* W3     = (const float*)d_in[5];
    const float* b3     = (const float*)d_in[6];
    const float* bias   = (const float*)d_in[7];
    float* out = (float*)d_out;

    nam_pre<<<NF, 32>>>(W1, b1, W2, b2, W3);

    cudaLaunchConfig_t cfg = {};
    cfg.gridDim  = dim3(GRID, 1, 1);
    cfg.blockDim = dim3(128, 1, 1);
    cfg.dynamicSmemBytes = 0;
    cfg.stream = 0;  // same (legacy default) stream as nam_pre
    cudaLaunchAttribute attr[1];
    attr[0].id = cudaLaunchAttributeProgrammaticStreamSerialization;
    attr[0].val.programmaticStreamSerializationAllowed = 1;
    cfg.attrs = attr;
    cfg.numAttrs = 1;
    cudaLaunchKernelEx(&cfg, nam_main,
                       inputs, W1, b1, W2, b2, W3, b3, bias, out);
}